// round 3
// baseline (speedup 1.0000x reference)
#include <cuda_runtime.h>
#include <cuda_bf16.h>

#define N_NODES 100000
#define N_EDGES 1600000
#define DIM     128
#define TM      64
#define SH_STRIDE 132   // padded row stride for h/t tiles (kills bank conflicts)

// ---------------- scratch (no allocations allowed) ----------------
__device__ int g_deg[N_NODES];
__device__ int g_rowptr[N_NODES + 1];
__device__ int g_wcur[N_NODES];
__device__ int g_esrc[N_EDGES];
__device__ __align__(16) float g_bufA[(size_t)N_NODES * DIM];
__device__ __align__(16) float g_bufB[(size_t)N_NODES * DIM];

// ---------------- CSR build ----------------
__global__ void zero_deg_kernel() {
    int i = blockIdx.x * blockDim.x + threadIdx.x;
    if (i < N_NODES) g_deg[i] = 0;
}

__global__ void count_kernel(const int* __restrict__ ei) {
    int e = blockIdx.x * blockDim.x + threadIdx.x;
    if (e < N_EDGES) atomicAdd(&g_deg[ei[N_EDGES + e]], 1);
}

__global__ void scan_kernel() {
    __shared__ int s[1024];
    int tid = threadIdx.x;
    const int per = (N_NODES + 1023) / 1024;   // 98
    int start = tid * per;
    int end = min(start + per, N_NODES);
    int sum = 0;
    for (int i = start; i < end; i++) sum += g_deg[i];
    s[tid] = sum;
    __syncthreads();
    #pragma unroll
    for (int off = 1; off < 1024; off <<= 1) {
        int v = (tid >= off) ? s[tid - off] : 0;
        __syncthreads();
        s[tid] += v;
        __syncthreads();
    }
    int run = (tid == 0) ? 0 : s[tid - 1];
    for (int i = start; i < end; i++) {
        g_rowptr[i] = run;
        g_wcur[i]   = run;
        run += g_deg[i];
    }
    if (tid == 0) g_rowptr[N_NODES] = s[1023];
}

__global__ void fill_kernel(const int* __restrict__ ei) {
    int e = blockIdx.x * blockDim.x + threadIdx.x;
    if (e < N_EDGES) {
        int d = ei[N_EDGES + e];
        int pos = atomicAdd(&g_wcur[d], 1);
        g_esrc[pos] = ei[e];
    }
}

// ---------------- aggregation: one warp per node, h = x + sum_{j in N} x_j ----------------
__global__ void agg_kernel(const float4* __restrict__ x, float4* __restrict__ out) {
    int gw = (blockIdx.x * blockDim.x + threadIdx.x) >> 5;
    if (gw >= N_NODES) return;
    int lane = threadIdx.x & 31;
    float4 acc = x[(size_t)gw * 32 + lane];     // self term (eps=0 GIN)
    int beg = g_rowptr[gw];
    int end = g_rowptr[gw + 1];
    for (int e = beg; e < end; e++) {
        int s = g_esrc[e];
        float4 v = __ldg(&x[(size_t)s * 32 + lane]);
        acc.x += v.x; acc.y += v.y; acc.z += v.z; acc.w += v.w;
    }
    out[(size_t)gw * 32 + lane] = acc;
}

// ---------------- fused MLP: out = [relu]( relu(h@W1+b1) @ W2 + b2 ) ----------------
__global__ void __launch_bounds__(256, 1)
mlp_kernel(const float* __restrict__ h,
           const float* __restrict__ W1, const float* __restrict__ b1,
           const float* __restrict__ W2, const float* __restrict__ b2,
           float* __restrict__ out, int relu_out)
{
    extern __shared__ float sm[];
    float* sW1 = sm;                    // 128*128
    float* sW2 = sm + 16384;            // 128*128
    float* sB1 = sm + 32768;            // 128
    float* sB2 = sB1 + 128;             // 128
    float* sH  = sB2 + 128;             // TM*SH_STRIDE
    float* sT  = sH + TM * SH_STRIDE;   // TM*SH_STRIDE

    int tid = threadIdx.x;
    for (int i = tid; i < 16384; i += 256) { sW1[i] = W1[i]; sW2[i] = W2[i]; }
    if (tid < 128) { sB1[tid] = b1[tid]; sB2[tid] = b2[tid]; }
    __syncthreads();

    int tx = tid & 15;        // 16 column groups
    int ty = tid >> 4;        // 16 row groups
    int c0 = tx * 8;
    int r0 = ty * 4;

    const int ntiles = (N_NODES + TM - 1) / TM;
    for (int t = blockIdx.x; t < ntiles; t += gridDim.x) {
        int row0 = t * TM;
        int rows = min(TM, N_NODES - row0);

        // stage h tile (zero-padded tail)
        for (int i = tid; i < TM * 32; i += 256) {
            int r = i >> 5, c4 = i & 31;
            float4 v = (r < rows)
                ? ((const float4*)(h + (size_t)(row0 + r) * DIM))[c4]
                : make_float4(0.f, 0.f, 0.f, 0.f);
            float* dst = &sH[r * SH_STRIDE + c4 * 4];
            dst[0] = v.x; dst[1] = v.y; dst[2] = v.z; dst[3] = v.w;
        }
        __syncthreads();

        // GEMM1: t = relu(h @ W1 + b1)
        {
            float acc[4][8];
            #pragma unroll
            for (int i = 0; i < 4; i++)
                #pragma unroll
                for (int j = 0; j < 8; j++) acc[i][j] = 0.f;

            #pragma unroll 4
            for (int k = 0; k < 128; k++) {
                float4 w0 = *(const float4*)&sW1[k * 128 + c0];
                float4 w1 = *(const float4*)&sW1[k * 128 + c0 + 4];
                float a0 = sH[(r0 + 0) * SH_STRIDE + k];
                float a1 = sH[(r0 + 1) * SH_STRIDE + k];
                float a2 = sH[(r0 + 2) * SH_STRIDE + k];
                float a3 = sH[(r0 + 3) * SH_STRIDE + k];
                acc[0][0] += a0 * w0.x; acc[0][1] += a0 * w0.y; acc[0][2] += a0 * w0.z; acc[0][3] += a0 * w0.w;
                acc[0][4] += a0 * w1.x; acc[0][5] += a0 * w1.y; acc[0][6] += a0 * w1.z; acc[0][7] += a0 * w1.w;
                acc[1][0] += a1 * w0.x; acc[1][1] += a1 * w0.y; acc[1][2] += a1 * w0.z; acc[1][3] += a1 * w0.w;
                acc[1][4] += a1 * w1.x; acc[1][5] += a1 * w1.y; acc[1][6] += a1 * w1.z; acc[1][7] += a1 * w1.w;
                acc[2][0] += a2 * w0.x; acc[2][1] += a2 * w0.y; acc[2][2] += a2 * w0.z; acc[2][3] += a2 * w0.w;
                acc[2][4] += a2 * w1.x; acc[2][5] += a2 * w1.y; acc[2][6] += a2 * w1.z; acc[2][7] += a2 * w1.w;
                acc[3][0] += a3 * w0.x; acc[3][1] += a3 * w0.y; acc[3][2] += a3 * w0.z; acc[3][3] += a3 * w0.w;
                acc[3][4] += a3 * w1.x; acc[3][5] += a3 * w1.y; acc[3][6] += a3 * w1.z; acc[3][7] += a3 * w1.w;
            }
            #pragma unroll
            for (int i = 0; i < 4; i++)
                #pragma unroll
                for (int j = 0; j < 8; j++) {
                    float v = acc[i][j] + sB1[c0 + j];
                    sT[(r0 + i) * SH_STRIDE + c0 + j] = fmaxf(v, 0.f);
                }
        }
        __syncthreads();

        // GEMM2: out = t @ W2 + b2 (+relu)
        {
            float acc[4][8];
            #pragma unroll
            for (int i = 0; i < 4; i++)
                #pragma unroll
                for (int j = 0; j < 8; j++) acc[i][j] = 0.f;

            #pragma unroll 4
            for (int k = 0; k < 128; k++) {
                float4 w0 = *(const float4*)&sW2[k * 128 + c0];
                float4 w1 = *(const float4*)&sW2[k * 128 + c0 + 4];
                float a0 = sT[(r0 + 0) * SH_STRIDE + k];
                float a1 = sT[(r0 + 1) * SH_STRIDE + k];
                float a2 = sT[(r0 + 2) * SH_STRIDE + k];
                float a3 = sT[(r0 + 3) * SH_STRIDE + k];
                acc[0][0] += a0 * w0.x; acc[0][1] += a0 * w0.y; acc[0][2] += a0 * w0.z; acc[0][3] += a0 * w0.w;
                acc[0][4] += a0 * w1.x; acc[0][5] += a0 * w1.y; acc[0][6] += a0 * w1.z; acc[0][7] += a0 * w1.w;
                acc[1][0] += a1 * w0.x; acc[1][1] += a1 * w0.y; acc[1][2] += a1 * w0.z; acc[1][3] += a1 * w0.w;
                acc[1][4] += a1 * w1.x; acc[1][5] += a1 * w1.y; acc[1][6] += a1 * w1.z; acc[1][7] += a1 * w1.w;
                acc[2][0] += a2 * w0.x; acc[2][1] += a2 * w0.y; acc[2][2] += a2 * w0.z; acc[2][3] += a2 * w0.w;
                acc[2][4] += a2 * w1.x; acc[2][5] += a2 * w1.y; acc[2][6] += a2 * w1.z; acc[2][7] += a2 * w1.w;
                acc[3][0] += a3 * w0.x; acc[3][1] += a3 * w0.y; acc[3][2] += a3 * w0.z; acc[3][3] += a3 * w0.w;
                acc[3][4] += a3 * w1.x; acc[3][5] += a3 * w1.y; acc[3][6] += a3 * w1.z; acc[3][7] += a3 * w1.w;
            }
            #pragma unroll
            for (int i = 0; i < 4; i++) {
                int r = r0 + i;
                if (r < rows) {
                    float o[8];
                    #pragma unroll
                    for (int j = 0; j < 8; j++) {
                        float v = acc[i][j] + sB2[c0 + j];
                        o[j] = relu_out ? fmaxf(v, 0.f) : v;
                    }
                    float* dst = out + (size_t)(row0 + r) * DIM + c0;
                    *(float4*)(dst)     = make_float4(o[0], o[1], o[2], o[3]);
                    *(float4*)(dst + 4) = make_float4(o[4], o[5], o[6], o[7]);
                }
            }
        }
        __syncthreads();
    }
}

// ---------------- launch ----------------
extern "C" void kernel_launch(void* const* d_in, const int* in_sizes, int n_in,
                              void* d_out, int out_size)
{
    const float* x  = (const float*)d_in[0];
    const int*   ei = (const int*)d_in[1];
    const float* W1 = (const float*)d_in[2];
    const float* b1 = (const float*)d_in[3];
    const float* W2 = (const float*)d_in[4];
    const float* b2 = (const float*)d_in[5];
    float* out = (float*)d_out;

    const int smem = (16384 * 2 + 256 + 2 * TM * SH_STRIDE) * sizeof(float);

    // One-time address/attribute setup (pure caching; no device-state or
    // work-dependence — kernel_launch remains deterministic + capture-safe).
    static float* bufA = nullptr;
    static float* bufB = nullptr;
    if (!bufA) {
        void *pA, *pB;
        cudaGetSymbolAddress(&pA, g_bufA);
        cudaGetSymbolAddress(&pB, g_bufB);
        bufA = (float*)pA;
        bufB = (float*)pB;
        cudaFuncSetAttribute(mlp_kernel, cudaFuncAttributeMaxDynamicSharedMemorySize, smem);
    }

    // CSR build (once per call; reused for all 3 layers)
    zero_deg_kernel<<<(N_NODES + 255) / 256, 256>>>();
    count_kernel<<<(N_EDGES + 255) / 256, 256>>>(ei);
    scan_kernel<<<1, 1024>>>();
    fill_kernel<<<(N_EDGES + 255) / 256, 256>>>(ei);

    const int agg_grid = (N_NODES * 32 + 255) / 256;

    // layer 0
    agg_kernel<<<agg_grid, 256>>>((const float4*)x, (float4*)bufB);
    mlp_kernel<<<148, 256, smem>>>(bufB, W1, b1, W2, b2, bufA, 1);
    // layer 1
    agg_kernel<<<agg_grid, 256>>>((const float4*)bufA, (float4*)bufB);
    mlp_kernel<<<148, 256, smem>>>(bufB, W1 + 16384, b1 + 128, W2 + 16384, b2 + 128, bufA, 1);
    // layer 2
    agg_kernel<<<agg_grid, 256>>>((const float4*)bufA, (float4*)bufB);
    mlp_kernel<<<148, 256, smem>>>(bufB, W1 + 32768, b1 + 256, W2 + 32768, b2 + 256, out, 0);
}

// round 5
// speedup vs baseline: 1.7634x; 1.7634x over previous
#include <cuda_runtime.h>
#include <cstdint>

#define N_NODES 100000
#define N_EDGES 1600000
#define DIM     128

// ---------------- scratch (no allocations allowed) ----------------
__device__ int g_deg[N_NODES];
__device__ int g_rowptr[N_NODES + 1];
__device__ int g_wcur[N_NODES];
__device__ int g_esrc[N_EDGES];
__device__ __align__(16) float g_bufA[(size_t)N_NODES * DIM];
__device__ __align__(16) float g_bufB[(size_t)N_NODES * DIM];

// ---------------- CSR build ----------------
__global__ void zero_deg_kernel() {
    int i = blockIdx.x * blockDim.x + threadIdx.x;
    if (i < N_NODES) g_deg[i] = 0;
}

__global__ void count_kernel(const int* __restrict__ ei) {
    int e = blockIdx.x * blockDim.x + threadIdx.x;
    if (e < N_EDGES) atomicAdd(&g_deg[ei[N_EDGES + e]], 1);
}

__global__ void scan_kernel() {
    __shared__ int s[1024];
    int tid = threadIdx.x;
    const int per = (N_NODES + 1023) / 1024;
    int start = tid * per;
    int end = min(start + per, N_NODES);
    int sum = 0;
    for (int i = start; i < end; i++) sum += g_deg[i];
    s[tid] = sum;
    __syncthreads();
    #pragma unroll
    for (int off = 1; off < 1024; off <<= 1) {
        int v = (tid >= off) ? s[tid - off] : 0;
        __syncthreads();
        s[tid] += v;
        __syncthreads();
    }
    int run = (tid == 0) ? 0 : s[tid - 1];
    for (int i = start; i < end; i++) {
        g_rowptr[i] = run;
        g_wcur[i]   = run;
        run += g_deg[i];
    }
    if (tid == 0) g_rowptr[N_NODES] = s[1023];
}

__global__ void fill_kernel(const int* __restrict__ ei) {
    int e = blockIdx.x * blockDim.x + threadIdx.x;
    if (e < N_EDGES) {
        int d = ei[N_EDGES + e];
        int pos = atomicAdd(&g_wcur[d], 1);
        g_esrc[pos] = ei[e];
    }
}

// ---------------- aggregation: one warp per node ----------------
__global__ void agg_kernel(const float4* __restrict__ x, float4* __restrict__ out) {
    int gw = (blockIdx.x * blockDim.x + threadIdx.x) >> 5;
    if (gw >= N_NODES) return;
    int lane = threadIdx.x & 31;
    float4 acc = x[(size_t)gw * 32 + lane];
    int beg = g_rowptr[gw];
    int end = g_rowptr[gw + 1];
    for (int e = beg; e < end; e++) {
        int s = g_esrc[e];
        float4 v = __ldg(&x[(size_t)s * 32 + lane]);
        acc.x += v.x; acc.y += v.y; acc.z += v.z; acc.w += v.w;
    }
    out[(size_t)gw * 32 + lane] = acc;
}

// ================= mma.sync tf32 fused MLP (sm_100-legal, no tcgen05) =================
// Per 128-row tile: each of 8 warps owns a 16-row slab end-to-end.
// D1 = relu(A @ W1 + b1) -> same smem rows; D2 = D1' @ W2 + b2 (+relu) -> gmem.
// SMEM: sH fp32 [128][132], sW1/sW2 tf32-bits [128(k)][132(n)], biases.

#define W_STRIDE 132
#define SM_H   0
#define SM_W1  (128 * W_STRIDE * 4)
#define SM_W2  (2 * 128 * W_STRIDE * 4)
#define SM_B   (3 * 128 * W_STRIDE * 4)
#define MLP_SMEM (SM_B + 1024)

__device__ __forceinline__ uint32_t f2tf32(float f) {
    uint32_t r;
    asm("cvt.rna.tf32.f32 %0, %1;" : "=r"(r) : "f"(f));
    return r;
}

__device__ __forceinline__ void mma16n8k8(float* c,
                                          uint32_t a0, uint32_t a1, uint32_t a2, uint32_t a3,
                                          uint32_t b0, uint32_t b1) {
    asm volatile(
        "mma.sync.aligned.m16n8k8.row.col.f32.tf32.tf32.f32 "
        "{%0,%1,%2,%3}, {%4,%5,%6,%7}, {%8,%9}, {%0,%1,%2,%3};"
        : "+f"(c[0]), "+f"(c[1]), "+f"(c[2]), "+f"(c[3])
        : "r"(a0), "r"(a1), "r"(a2), "r"(a3), "r"(b0), "r"(b1));
}

__global__ void __launch_bounds__(256, 1)
mlp_mma(const float* __restrict__ h,
        const float* __restrict__ W1, const float* __restrict__ b1,
        const float* __restrict__ W2, const float* __restrict__ b2,
        float* __restrict__ out, int relu_out)
{
    extern __shared__ __align__(16) char sm[];
    float*    sH  = (float*)(sm + SM_H);
    uint32_t* sW1 = (uint32_t*)(sm + SM_W1);
    uint32_t* sW2 = (uint32_t*)(sm + SM_W2);
    float*    sB1 = (float*)(sm + SM_B);
    float*    sB2 = sB1 + 128;

    const int tid  = threadIdx.x;
    const int wid  = tid >> 5;
    const int lane = tid & 31;
    const int gid  = lane >> 2;   // 0..7
    const int tig  = lane & 3;    // 0..3

    // stage weights as tf32 bits, [k][n] stride 132
    for (int i = tid; i < 16384; i += 256) {
        int k = i >> 7, n = i & 127;
        sW1[k * W_STRIDE + n] = f2tf32(W1[i]);
        sW2[k * W_STRIDE + n] = f2tf32(W2[i]);
    }
    if (tid < 128) { sB1[tid] = b1[tid]; sB2[tid] = b2[tid]; }
    __syncthreads();

    const int m0 = wid * 16;
    const int ntiles = (N_NODES + 127) / 128;

    for (int t = blockIdx.x; t < ntiles; t += gridDim.x) {
        const int row0 = t * 128;

        // ---- stage this warp's 16 rows (fp32, zero-padded) ----
        __syncwarp();   // prior-tile GEMM2 reads of sH must be done before overwrite
        #pragma unroll 4
        for (int r = 0; r < 16; r++) {
            int gr = row0 + m0 + r;
            float4 v = (gr < N_NODES) ? *(const float4*)(h + (size_t)gr * DIM + lane * 4)
                                      : make_float4(0.f, 0.f, 0.f, 0.f);
            *(float4*)(sH + (m0 + r) * W_STRIDE + lane * 4) = v;
        }
        __syncwarp();

        float acc[16][4];
        #pragma unroll
        for (int f = 0; f < 16; f++) { acc[f][0] = acc[f][1] = acc[f][2] = acc[f][3] = 0.f; }

        // ---- GEMM1: acc = A @ W1 ----
        const float* arow = sH + (m0 + gid) * W_STRIDE;
        #pragma unroll 2
        for (int ks = 0; ks < 16; ks++) {
            const int k0 = ks * 8;
            uint32_t a0 = f2tf32(arow[k0 + tig]);
            uint32_t a1 = f2tf32(arow[8 * W_STRIDE + k0 + tig]);
            uint32_t a2 = f2tf32(arow[k0 + tig + 4]);
            uint32_t a3 = f2tf32(arow[8 * W_STRIDE + k0 + tig + 4]);
            const uint32_t* bk0 = sW1 + (k0 + tig) * W_STRIDE + gid;
            const uint32_t* bk1 = bk0 + 4 * W_STRIDE;
            #pragma unroll
            for (int f = 0; f < 16; f++)
                mma16n8k8(acc[f], a0, a1, a2, a3, bk0[f * 8], bk1[f * 8]);
        }

        // ---- epilogue1: relu(acc + b1) -> same smem rows ----
        __syncwarp();   // all lanes finished reading sH for GEMM1
        #pragma unroll
        for (int f = 0; f < 16; f++) {
            int col = 8 * f + 2 * tig;
            float v0 = fmaxf(acc[f][0] + sB1[col],     0.f);
            float v1 = fmaxf(acc[f][1] + sB1[col + 1], 0.f);
            float v2 = fmaxf(acc[f][2] + sB1[col],     0.f);
            float v3 = fmaxf(acc[f][3] + sB1[col + 1], 0.f);
            *(float2*)(sH + (m0 + gid) * W_STRIDE + col)     = make_float2(v0, v1);
            *(float2*)(sH + (m0 + gid + 8) * W_STRIDE + col) = make_float2(v2, v3);
        }
        __syncwarp();

        #pragma unroll
        for (int f = 0; f < 16; f++) { acc[f][0] = acc[f][1] = acc[f][2] = acc[f][3] = 0.f; }

        // ---- GEMM2: acc = T @ W2 ----
        #pragma unroll 2
        for (int ks = 0; ks < 16; ks++) {
            const int k0 = ks * 8;
            uint32_t a0 = f2tf32(arow[k0 + tig]);
            uint32_t a1 = f2tf32(arow[8 * W_STRIDE + k0 + tig]);
            uint32_t a2 = f2tf32(arow[k0 + tig + 4]);
            uint32_t a3 = f2tf32(arow[8 * W_STRIDE + k0 + tig + 4]);
            const uint32_t* bk0 = sW2 + (k0 + tig) * W_STRIDE + gid;
            const uint32_t* bk1 = bk0 + 4 * W_STRIDE;
            #pragma unroll
            for (int f = 0; f < 16; f++)
                mma16n8k8(acc[f], a0, a1, a2, a3, bk0[f * 8], bk1[f * 8]);
        }

        // ---- epilogue2: acc + b2 (+relu) -> gmem ----
        const int gr0 = row0 + m0 + gid;
        const int gr1 = gr0 + 8;
        #pragma unroll
        for (int f = 0; f < 16; f++) {
            int col = 8 * f + 2 * tig;
            if (gr0 < N_NODES) {
                float v0 = acc[f][0] + sB2[col];
                float v1 = acc[f][1] + sB2[col + 1];
                if (relu_out) { v0 = fmaxf(v0, 0.f); v1 = fmaxf(v1, 0.f); }
                *(float2*)(out + (size_t)gr0 * DIM + col) = make_float2(v0, v1);
            }
            if (gr1 < N_NODES) {
                float v2 = acc[f][2] + sB2[col];
                float v3 = acc[f][3] + sB2[col + 1];
                if (relu_out) { v2 = fmaxf(v2, 0.f); v3 = fmaxf(v3, 0.f); }
                *(float2*)(out + (size_t)gr1 * DIM + col) = make_float2(v2, v3);
            }
        }
    }
}

// ---------------- launch ----------------
extern "C" void kernel_launch(void* const* d_in, const int* in_sizes, int n_in,
                              void* d_out, int out_size)
{
    const float* x  = (const float*)d_in[0];
    const int*   ei = (const int*)d_in[1];
    const float* W1 = (const float*)d_in[2];
    const float* b1 = (const float*)d_in[3];
    const float* W2 = (const float*)d_in[4];
    const float* b2 = (const float*)d_in[5];
    float* out = (float*)d_out;

    static float* bufA = nullptr;
    static float* bufB = nullptr;
    if (!bufA) {
        void *pA, *pB;
        cudaGetSymbolAddress(&pA, g_bufA);
        cudaGetSymbolAddress(&pB, g_bufB);
        bufA = (float*)pA;
        bufB = (float*)pB;
        cudaFuncSetAttribute(mlp_mma, cudaFuncAttributeMaxDynamicSharedMemorySize, MLP_SMEM);
    }

    // CSR build
    zero_deg_kernel<<<(N_NODES + 255) / 256, 256>>>();
    count_kernel<<<(N_EDGES + 255) / 256, 256>>>(ei);
    scan_kernel<<<1, 1024>>>();
    fill_kernel<<<(N_EDGES + 255) / 256, 256>>>(ei);

    const int agg_grid = (N_NODES * 32 + 255) / 256;

    // layer 0
    agg_kernel<<<agg_grid, 256>>>((const float4*)x, (float4*)bufB);
    mlp_mma<<<148, 256, MLP_SMEM>>>(bufB, W1, b1, W2, b2, bufA, 1);
    // layer 1
    agg_kernel<<<agg_grid, 256>>>((const float4*)bufA, (float4*)bufB);
    mlp_mma<<<148, 256, MLP_SMEM>>>(bufB, W1 + 16384, b1 + 128, W2 + 16384, b2 + 128, bufA, 1);
    // layer 2
    agg_kernel<<<agg_grid, 256>>>((const float4*)bufA, (float4*)bufB);
    mlp_mma<<<148, 256, MLP_SMEM>>>(bufB, W1 + 32768, b1 + 256, W2 + 32768, b2 + 256, out, 0);
}